// round 1
// baseline (speedup 1.0000x reference)
#include <cuda_runtime.h>
#include <math.h>

// ---------------------------------------------------------------------------
// DifferentiableFBP: ramp-filtered backprojection (fan-beam FBP)
//
// Stage 1 (prep):   per-batch scalars, sin/cos(beta) table, cos-weight table,
//                   spatial ram-lak taps h[d] (exact equivalent of the
//                   rfft*filt*irfft pipeline: filter is 2*FFT(f), f symmetric,
//                   pad 2048 >= 736+735 so it is a pure linear convolution).
// Stage 2 (conv):   filtered[a,k] = qscale * sum_m sino[a,m]*cosw[m]*h[|k-m|]
//                   (h zero at even d != 0  -> only 368 taps + center)
// Stage 3 (bp):     per pixel, sum over 1152 angles of lerp(q, u)*(dso_s/U)^2,
//                   then out = (reco - hu0) * 1000/(hu0+1e-6)
// ---------------------------------------------------------------------------

#define MAXB 4
#define AMAX 1536
#define DMAX 1024
#define CT   256   // conv block size (fixed, logic depends on it)

struct BParams {
    float dso_s;   // scaled source distance
    float c1;      // dso_s / du_v
    float center;  // (det-1)/2
    float qscale;  // vox * 0.5*dbeta / du_v  (all linear scales folded)
    float hu0;
    float oscale;  // 1000/(hu0+1e-6)
};

__device__ BParams g_par[MAXB];
__device__ float   g_h[DMAX];
__device__ float2  g_sc[MAXB * AMAX];          // (sin(beta), cos(beta))
__device__ float   g_cosw[MAXB * DMAX];
__device__ float   g_q[MAXB * AMAX * DMAX];    // filtered sinogram (compact index)

// ---------------------------------------------------------------- taps -----
__global__ void fill_h_kernel(int det) {
    for (int d = threadIdx.x; d < det; d += blockDim.x) {
        double v;
        if (d == 0)      v = 0.5;                                // 2 * 0.25
        else if (d & 1) { double pd = 3.14159265358979323846 * (double)d;
                          v = -2.0 / (pd * pd); }                // 2 * (-1/(pi d)^2)
        else             v = 0.0;
        g_h[d] = (float)v;
    }
}

// ------------------------------------------------------------- per-batch ---
__global__ void prep_kernel(const float* __restrict__ angles,
                            const float* __restrict__ dso,
                            const float* __restrict__ ddo,
                            const float* __restrict__ du,
                            const float* __restrict__ hu,
                            int Ahr, int Asr, int det) {
    int b = blockIdx.x;
    __shared__ float sh[4];
    if (threadIdx.x == 0) {
        const float vox = 1.0f / 0.7f;
        float dso_s = vox * dso[b];
        float sd_s  = vox * (dso[b] + ddo[b]);
        float du_s  = vox * du[b];
        float du_v  = du_s * dso_s / sd_s;
        float a0    = angles[(size_t)b * Ahr];
        float inc   = angles[(size_t)b * Ahr + 1] - a0;
        float dbeta = ((float)Ahr * inc) / (float)Asr;

        BParams p;
        p.dso_s  = dso_s;
        p.c1     = dso_s / du_v;
        p.center = 0.5f * (float)(det - 1);
        p.qscale = vox * 0.5f * dbeta / du_v;
        float h0 = fmaxf(fabsf(hu[b]), 1e-6f);
        p.hu0    = h0;
        p.oscale = 1000.0f / (h0 + 1e-6f);
        g_par[b] = p;

        sh[0] = dso_s; sh[1] = du_v; sh[2] = a0; sh[3] = dbeta;
    }
    __syncthreads();
    float dso_s = sh[0], du_v = sh[1], a0 = sh[2], dbeta = sh[3];

    for (int a = threadIdx.x; a < Asr; a += blockDim.x) {
        float bta = a0 + dbeta * (float)a;
        g_sc[b * Asr + a] = make_float2(sinf(bta), cosf(bta));
    }
    for (int m = threadIdx.x; m < det; m += blockDim.x) {
        float uk = ((float)m - 0.5f * (float)(det - 1)) * du_v;
        g_cosw[b * det + m] = dso_s / sqrtf(dso_s * dso_s + uk * uk);
    }
}

// ------------------------------------------------------------- filtering ---
// One block per (angle,batch) row. 256 threads, 3 outputs per thread:
// k = t, t+256, t+512.  h taps are zero at even |d|!=0, so loop only over
// detector samples m of parity opposite to k (368 iterations).
__global__ __launch_bounds__(CT) void conv_kernel(const float* __restrict__ sino,
                                                  int A, int det) {
    int a = blockIdx.x, b = blockIdx.y;
    __shared__ float s_sh[DMAX];
    __shared__ float h_ext[2 * DMAX];   // h_ext[i] = h[|i-(det-1)|], zero-padded

    const float* row = sino + ((size_t)b * A + a) * det;
    const float* cw  = g_cosw + b * det;
    for (int i = threadIdx.x; i < det; i += CT)
        s_sh[i] = row[i] * cw[i];
    int hw = 2 * det - 1;
    for (int i = threadIdx.x; i < 2 * DMAX; i += CT) {
        float v = 0.0f;
        if (i < hw) { int d = i - (det - 1); if (d < 0) d = -d; v = g_h[d]; }
        h_ext[i] = v;
    }
    __syncthreads();

    const float qs = g_par[b].qscale;
    const int t  = threadIdx.x;
    const int k0 = t, k1 = t + CT, k2 = t + 2 * CT;
    const bool v1 = (k1 < det), v2 = (k2 < det);

    float acc0 = 0.5f * s_sh[k0];
    float acc1 = v1 ? 0.5f * s_sh[k1] : 0.0f;
    float acc2 = v2 ? 0.5f * s_sh[k2] : 0.0f;

    const int base = k0 + (det - 1);
    const int m0   = (t & 1) ^ 1;       // opposite parity to k
#pragma unroll 4
    for (int m = m0; m < det; m += 2) {
        float sm = s_sh[m];
        int idx = base - m;
        acc0 = fmaf(sm, h_ext[idx],          acc0);
        acc1 = fmaf(sm, h_ext[idx + CT],     acc1);
        acc2 = fmaf(sm, h_ext[idx + 2 * CT], acc2);
    }

    float* qr = g_q + ((size_t)b * A + a) * det;
    qr[k0] = acc0 * qs;
    if (v1) qr[k1] = acc1 * qs;
    if (v2) qr[k2] = acc2 * qs;
}

// ---------------------------------------------------------- backprojection -
__device__ __forceinline__ float bp_sample(const float* __restrict__ qr,
                                           float U, float tt,
                                           float c1, float center,
                                           float dso_s, int det, float detm1) {
    float r  = __fdividef(1.0f, U);
    float u  = fmaf(c1 * tt, r, center);
    float fi = floorf(u);
    float w  = u - fi;
    int   i0 = (int)fi;
    int   ia = min(max(i0, 0), det - 1);
    int   ib = min(max(i0 + 1, 0), det - 1);
    float q0 = __ldg(qr + ia);
    float q1 = __ldg(qr + ib);
    float g  = dso_s * r; g *= g;
    float val = (q0 * (1.0f - w) + q1 * w) * g;
    return (u >= 0.0f && u <= detm1) ? val : 0.0f;
}

// Block (32,8) handles a 32x16 pixel tile (2 pixels/thread along y).
__global__ __launch_bounds__(256) void bp_kernel(float* __restrict__ out,
                                                 int A, int det, int N) {
    int b = blockIdx.z;
    __shared__ float2 sc[AMAX];
    int tid = threadIdx.y * 32 + threadIdx.x;
    for (int a = tid; a < A; a += 256) sc[a] = g_sc[b * A + a];
    __syncthreads();

    BParams p = g_par[b];
    int x  = blockIdx.x * 32 + threadIdx.x;
    int y0 = blockIdx.y * 16 + threadIdx.y;
    int y1 = y0 + 8;
    if (x >= N || y0 >= N) return;

    float half = 0.5f * (float)(N - 1);
    float X  = (float)x  - half;
    float Y0 = (float)y0 - half;
    const float detm1 = (float)(det - 1);
    const float* qb = g_q + (size_t)b * A * det;

    float acc0 = 0.0f, acc1 = 0.0f;
#pragma unroll 2
    for (int a = 0; a < A; a++) {
        float2 s = sc[a];
        float U0 = fmaf(-Y0, s.y, fmaf(X, s.x, p.dso_s));  // dso_s + X sin - Y cos
        float t0 = fmaf(X, s.y, Y0 * s.x);                 // X cos + Y sin
        float U1 = fmaf(-8.0f, s.y, U0);
        float t1 = fmaf( 8.0f, s.x, t0);
        const float* qr = qb + (size_t)a * det;
        acc0 += bp_sample(qr, U0, t0, p.c1, p.center, p.dso_s, det, detm1);
        acc1 += bp_sample(qr, U1, t1, p.c1, p.center, p.dso_s, det, detm1);
    }

    size_t obase = (size_t)b * N * N;
    out[obase + (size_t)y0 * N + x] = (acc0 - p.hu0) * p.oscale;
    if (y1 < N)
        out[obase + (size_t)y1 * N + x] = (acc1 - p.hu0) * p.oscale;
}

// ----------------------------------------------------------------- launch --
extern "C" void kernel_launch(void* const* d_in, const int* in_sizes, int n_in,
                              void* d_out, int out_size) {
    const float* sino   = (const float*)d_in[0];   // (B,1,A,DET)
    const float* angles = (const float*)d_in[1];   // (B,A_hr)
    const float* dso    = (const float*)d_in[2];
    const float* ddo    = (const float*)d_in[3];
    const float* du     = (const float*)d_in[4];
    const float* hu     = (const float*)d_in[5];
    float* out = (float*)d_out;

    int B   = in_sizes[2];
    int Ahr = in_sizes[1] / B;
    int Asr = Ahr;                         // same count in this problem
    int det = in_sizes[0] / (B * Asr);
    int per = out_size / B;
    int N = 1; while (N * N < per) N++;

    fill_h_kernel<<<1, 256>>>(det);
    prep_kernel<<<B, 256>>>(angles, dso, ddo, du, hu, Ahr, Asr, det);
    conv_kernel<<<dim3(Asr, B), CT>>>(sino, Asr, det);
    dim3 grid((N + 31) / 32, (N + 15) / 16, B);
    bp_kernel<<<grid, dim3(32, 8)>>>(out, Asr, det, N);
}

// round 2
// speedup vs baseline: 1.1725x; 1.1725x over previous
#include <cuda_runtime.h>
#include <math.h>

// ---------------------------------------------------------------------------
// DifferentiableFBP: ramp-filtered backprojection (fan-beam FBP)
// Stage 1 (prep):  per-batch scalars, per-angle float4 (sin,cos,-8cos,8*c1*sin),
//                  cos-weight table, spatial ram-lak taps (exact equivalent of
//                  the rfft pipeline: pure linear convolution, even taps zero).
// Stage 2 (conv):  filtered row conv, then paired float2 table q2[k]=(q[k],q[k+1]).
// Stage 3 (bp):    per pixel sum over angles of lerp(q,u)*(dso_s/U)^2.
// ---------------------------------------------------------------------------

#define MAXB 4
#define AMAX 1536
#define DMAX 1024
#define CT   256   // conv block size (fixed, logic depends on it)

struct BParams {
    float dso_s;   // scaled source distance
    float c1;      // dso_s / du_v
    float center;  // (det-1)/2
    float qscale;  // vox * 0.5*dbeta / du_v
    float hu0;
    float oscale;  // 1000/(hu0+1e-6)
    float dso2;    // dso_s^2
};

__device__ BParams g_par[MAXB];
__device__ float   g_h[DMAX];
__device__ float4  g_sc4[MAXB * AMAX];      // (sin, cos, -8*cos, 8*c1*sin)
__device__ float   g_cosw[MAXB * DMAX];
__device__ float2  g_q2[MAXB * AMAX * DMAX]; // paired filtered sinogram

// ---------------------------------------------------------------- taps -----
__global__ void fill_h_kernel(int det) {
    for (int d = threadIdx.x; d < det; d += blockDim.x) {
        double v;
        if (d == 0)      v = 0.5;
        else if (d & 1) { double pd = 3.14159265358979323846 * (double)d;
                          v = -2.0 / (pd * pd); }
        else             v = 0.0;
        g_h[d] = (float)v;
    }
}

// ------------------------------------------------------------- per-batch ---
__global__ void prep_kernel(const float* __restrict__ angles,
                            const float* __restrict__ dso,
                            const float* __restrict__ ddo,
                            const float* __restrict__ du,
                            const float* __restrict__ hu,
                            int Ahr, int Asr, int det) {
    int b = blockIdx.x;
    __shared__ float sh[5];
    if (threadIdx.x == 0) {
        const float vox = 1.0f / 0.7f;
        float dso_s = vox * dso[b];
        float sd_s  = vox * (dso[b] + ddo[b]);
        float du_s  = vox * du[b];
        float du_v  = du_s * dso_s / sd_s;
        float a0    = angles[(size_t)b * Ahr];
        float inc   = angles[(size_t)b * Ahr + 1] - a0;
        float dbeta = ((float)Ahr * inc) / (float)Asr;

        BParams p;
        p.dso_s  = dso_s;
        p.c1     = dso_s / du_v;
        p.center = 0.5f * (float)(det - 1);
        p.qscale = vox * 0.5f * dbeta / du_v;
        float h0 = fmaxf(fabsf(hu[b]), 1e-6f);
        p.hu0    = h0;
        p.oscale = 1000.0f / (h0 + 1e-6f);
        p.dso2   = dso_s * dso_s;
        g_par[b] = p;

        sh[0] = dso_s; sh[1] = du_v; sh[2] = a0; sh[3] = dbeta; sh[4] = p.c1;
    }
    __syncthreads();
    float dso_s = sh[0], du_v = sh[1], a0 = sh[2], dbeta = sh[3], c1 = sh[4];

    for (int a = threadIdx.x; a < Asr; a += blockDim.x) {
        float bta = a0 + dbeta * (float)a;
        float s = sinf(bta), c = cosf(bta);
        g_sc4[b * Asr + a] = make_float4(s, c, -8.0f * c, 8.0f * c1 * s);
    }
    for (int m = threadIdx.x; m < det; m += blockDim.x) {
        float uk = ((float)m - 0.5f * (float)(det - 1)) * du_v;
        g_cosw[b * det + m] = dso_s / sqrtf(dso_s * dso_s + uk * uk);
    }
}

// ------------------------------------------------------------- filtering ---
// One block per (angle,batch) row. 256 threads, 3 outputs per thread.
// h zero at even |d| != 0 -> only detector samples of opposite parity.
__global__ __launch_bounds__(CT) void conv_kernel(const float* __restrict__ sino,
                                                  int A, int det) {
    int a = blockIdx.x, b = blockIdx.y;
    __shared__ float s_sh[DMAX];
    __shared__ float h_ext[2 * DMAX];

    const float* row = sino + ((size_t)b * A + a) * det;
    const float* cw  = g_cosw + b * det;
    for (int i = threadIdx.x; i < det; i += CT)
        s_sh[i] = row[i] * cw[i];
    int hw = 2 * det - 1;
    for (int i = threadIdx.x; i < 2 * DMAX; i += CT) {
        float v = 0.0f;
        if (i < hw) { int d = i - (det - 1); if (d < 0) d = -d; v = g_h[d]; }
        h_ext[i] = v;
    }
    __syncthreads();

    const float qs = g_par[b].qscale;
    const int t  = threadIdx.x;
    const int k0 = t, k1 = t + CT, k2 = t + 2 * CT;
    const bool v1 = (k1 < det), v2 = (k2 < det);

    float acc0 = 0.5f * s_sh[k0];
    float acc1 = v1 ? 0.5f * s_sh[k1] : 0.0f;
    float acc2 = v2 ? 0.5f * s_sh[k2] : 0.0f;

    const int base = k0 + (det - 1);
    const int m0   = (t & 1) ^ 1;
#pragma unroll 4
    for (int m = m0; m < det; m += 2) {
        float sm = s_sh[m];
        int idx = base - m;
        acc0 = fmaf(sm, h_ext[idx],          acc0);
        acc1 = fmaf(sm, h_ext[idx + CT],     acc1);
        acc2 = fmaf(sm, h_ext[idx + 2 * CT], acc2);
    }

    // stage outputs in shared, then emit paired float2 table
    __syncthreads();
    s_sh[k0] = acc0 * qs;
    if (v1) s_sh[k1] = acc1 * qs;
    if (v2) s_sh[k2] = acc2 * qs;
    __syncthreads();

    float2* qr = g_q2 + ((size_t)b * A + a) * det;
    for (int i = threadIdx.x; i < det; i += CT) {
        int j = (i + 1 < det) ? i + 1 : det - 1;
        qr[i] = make_float2(s_sh[i], s_sh[j]);
    }
}

// ---------------------------------------------------------- backprojection -
// Block (32,8) handles a 32x32 pixel tile (4 pixels/thread along y, spacing 8).
__global__ __launch_bounds__(256) void bp_kernel(float* __restrict__ out,
                                                 int A, int det, int N) {
    int b = blockIdx.z;
    __shared__ float4 sc[AMAX];
    int tid = threadIdx.y * 32 + threadIdx.x;
    for (int a = tid; a < A; a += 256) sc[a] = g_sc4[b * A + a];
    __syncthreads();

    BParams p = g_par[b];
    int x  = blockIdx.x * 32 + threadIdx.x;
    int y0 = blockIdx.y * 32 + threadIdx.y;

    float half = 0.5f * (float)(N - 1);
    float X  = (float)x  - half;
    float Y0 = (float)y0 - half;
    float Xp = p.c1 * X;      // fold c1 into coords: u = t'/U + center
    float Yp = p.c1 * Y0;
    const float detm1 = (float)(det - 1);
    const float dso2  = p.dso2;
    const float dso_s = p.dso_s;
    const float center = p.center;
    const float2* __restrict__ qb = g_q2 + (size_t)b * A * det;

    float acc0 = 0.0f, acc1 = 0.0f, acc2 = 0.0f, acc3 = 0.0f;
    const float2* qr = qb;

#pragma unroll 2
    for (int a = 0; a < A; a++) {
        float4 s = sc[a];
        float U = fmaf(-Y0, s.y, fmaf(X, s.x, dso_s));  // dso_s + X sin - Y cos
        float T = fmaf(Xp, s.y, Yp * s.x);              // c1*(X cos + Y sin)

        {   // y0
            float r  = __fdividef(1.0f, U);
            float u  = fmaf(T, r, center);
            float uc = fminf(fmaxf(u, 0.0f), detm1);
            float fi = floorf(uc);
            int   i  = (int)fi;
            float w  = uc - fi;
            float2 q = __ldg(qr + i);
            float lerp = fmaf(w, q.y - q.x, q.x);
            float g = dso2 * (r * r);
            g = (u == uc) ? g : 0.0f;
            acc0 = fmaf(lerp, g, acc0);
        }
        U += s.z; T += s.w;
        {   // y0+8
            float r  = __fdividef(1.0f, U);
            float u  = fmaf(T, r, center);
            float uc = fminf(fmaxf(u, 0.0f), detm1);
            float fi = floorf(uc);
            int   i  = (int)fi;
            float w  = uc - fi;
            float2 q = __ldg(qr + i);
            float lerp = fmaf(w, q.y - q.x, q.x);
            float g = dso2 * (r * r);
            g = (u == uc) ? g : 0.0f;
            acc1 = fmaf(lerp, g, acc1);
        }
        U += s.z; T += s.w;
        {   // y0+16
            float r  = __fdividef(1.0f, U);
            float u  = fmaf(T, r, center);
            float uc = fminf(fmaxf(u, 0.0f), detm1);
            float fi = floorf(uc);
            int   i  = (int)fi;
            float w  = uc - fi;
            float2 q = __ldg(qr + i);
            float lerp = fmaf(w, q.y - q.x, q.x);
            float g = dso2 * (r * r);
            g = (u == uc) ? g : 0.0f;
            acc2 = fmaf(lerp, g, acc2);
        }
        U += s.z; T += s.w;
        {   // y0+24
            float r  = __fdividef(1.0f, U);
            float u  = fmaf(T, r, center);
            float uc = fminf(fmaxf(u, 0.0f), detm1);
            float fi = floorf(uc);
            int   i  = (int)fi;
            float w  = uc - fi;
            float2 q = __ldg(qr + i);
            float lerp = fmaf(w, q.y - q.x, q.x);
            float g = dso2 * (r * r);
            g = (u == uc) ? g : 0.0f;
            acc3 = fmaf(lerp, g, acc3);
        }
        qr += det;
    }

    size_t obase = (size_t)b * N * N;
    out[obase + (size_t)(y0     ) * N + x] = (acc0 - p.hu0) * p.oscale;
    out[obase + (size_t)(y0 +  8) * N + x] = (acc1 - p.hu0) * p.oscale;
    out[obase + (size_t)(y0 + 16) * N + x] = (acc2 - p.hu0) * p.oscale;
    out[obase + (size_t)(y0 + 24) * N + x] = (acc3 - p.hu0) * p.oscale;
}

// ----------------------------------------------------------------- launch --
extern "C" void kernel_launch(void* const* d_in, const int* in_sizes, int n_in,
                              void* d_out, int out_size) {
    const float* sino   = (const float*)d_in[0];   // (B,1,A,DET)
    const float* angles = (const float*)d_in[1];   // (B,A_hr)
    const float* dso    = (const float*)d_in[2];
    const float* ddo    = (const float*)d_in[3];
    const float* du     = (const float*)d_in[4];
    const float* hu     = (const float*)d_in[5];
    float* out = (float*)d_out;

    int B   = in_sizes[2];
    int Ahr = in_sizes[1] / B;
    int Asr = Ahr;
    int det = in_sizes[0] / (B * Asr);
    int per = out_size / B;
    int N = 1; while (N * N < per) N++;

    fill_h_kernel<<<1, 256>>>(det);
    prep_kernel<<<B, 256>>>(angles, dso, ddo, du, hu, Ahr, Asr, det);
    conv_kernel<<<dim3(Asr, B), CT>>>(sino, Asr, det);
    dim3 grid((N + 31) / 32, (N + 31) / 32, B);
    bp_kernel<<<grid, dim3(32, 8)>>>(out, Asr, det, N);
}

// round 3
// speedup vs baseline: 1.2784x; 1.0904x over previous
#include <cuda_runtime.h>
#include <math.h>

// ---------------------------------------------------------------------------
// DifferentiableFBP: ramp-filtered backprojection (fan-beam FBP)
// Stage 1 (prep):  per-batch scalars, per-angle float4 (sin,cos,-8cos,8*c1*sin),
//                  cos-weight table, spatial ram-lak taps (exact equivalent of
//                  the rfft pipeline: pure linear convolution, even taps zero).
// Stage 2 (conv):  filtered row conv, then paired float2 table q2[k]=(q[k],q[k+1]).
// Stage 3 (bp):    per pixel sum over angles of lerp(q,u)*(dso_s/U)^2.
// ---------------------------------------------------------------------------

#define MAXB 4
#define AMAX 1536
#define DMAX 1024
#define CT   256   // conv block size (fixed, logic depends on it)

struct BParams {
    float dso_s;   // scaled source distance
    float c1;      // dso_s / du_v
    float center;  // (det-1)/2
    float qscale;  // vox * 0.5*dbeta / du_v
    float hu0;
    float oscale;  // 1000/(hu0+1e-6)
    float dso2;    // dso_s^2
};

__device__ BParams g_par[MAXB];
__device__ float   g_h[DMAX];
__device__ float4  g_sc4[MAXB * AMAX];      // (sin, cos, -8*cos, 8*c1*sin)
__device__ float   g_cosw[MAXB * DMAX];
__device__ float2  g_q2[MAXB * AMAX * DMAX]; // paired filtered sinogram

// ---------------------------------------------------------------- taps -----
__global__ void fill_h_kernel(int det) {
    for (int d = threadIdx.x; d < det; d += blockDim.x) {
        double v;
        if (d == 0)      v = 0.5;
        else if (d & 1) { double pd = 3.14159265358979323846 * (double)d;
                          v = -2.0 / (pd * pd); }
        else             v = 0.0;
        g_h[d] = (float)v;
    }
}

// ------------------------------------------------------------- per-batch ---
__global__ void prep_kernel(const float* __restrict__ angles,
                            const float* __restrict__ dso,
                            const float* __restrict__ ddo,
                            const float* __restrict__ du,
                            const float* __restrict__ hu,
                            int Ahr, int Asr, int det) {
    int b = blockIdx.x;
    __shared__ float sh[5];
    if (threadIdx.x == 0) {
        const float vox = 1.0f / 0.7f;
        float dso_s = vox * dso[b];
        float sd_s  = vox * (dso[b] + ddo[b]);
        float du_s  = vox * du[b];
        float du_v  = du_s * dso_s / sd_s;
        float a0    = angles[(size_t)b * Ahr];
        float inc   = angles[(size_t)b * Ahr + 1] - a0;
        float dbeta = ((float)Ahr * inc) / (float)Asr;

        BParams p;
        p.dso_s  = dso_s;
        p.c1     = dso_s / du_v;
        p.center = 0.5f * (float)(det - 1);
        p.qscale = vox * 0.5f * dbeta / du_v;
        float h0 = fmaxf(fabsf(hu[b]), 1e-6f);
        p.hu0    = h0;
        p.oscale = 1000.0f / (h0 + 1e-6f);
        p.dso2   = dso_s * dso_s;
        g_par[b] = p;

        sh[0] = dso_s; sh[1] = du_v; sh[2] = a0; sh[3] = dbeta; sh[4] = p.c1;
    }
    __syncthreads();
    float dso_s = sh[0], du_v = sh[1], a0 = sh[2], dbeta = sh[3], c1 = sh[4];

    for (int a = threadIdx.x; a < Asr; a += blockDim.x) {
        float bta = a0 + dbeta * (float)a;
        float s = sinf(bta), c = cosf(bta);
        g_sc4[b * Asr + a] = make_float4(s, c, -8.0f * c, 8.0f * c1 * s);
    }
    for (int m = threadIdx.x; m < det; m += blockDim.x) {
        float uk = ((float)m - 0.5f * (float)(det - 1)) * du_v;
        g_cosw[b * det + m] = dso_s / sqrtf(dso_s * dso_s + uk * uk);
    }
}

// ------------------------------------------------------------- filtering ---
// One block per (angle,batch) row. 256 threads, 3 outputs per thread.
// h zero at even |d| != 0 -> only detector samples of opposite parity.
__global__ __launch_bounds__(CT) void conv_kernel(const float* __restrict__ sino,
                                                  int A, int det) {
    int a = blockIdx.x, b = blockIdx.y;
    __shared__ float s_sh[DMAX];
    __shared__ float h_ext[2 * DMAX];

    const float* row = sino + ((size_t)b * A + a) * det;
    const float* cw  = g_cosw + b * det;
    for (int i = threadIdx.x; i < det; i += CT)
        s_sh[i] = row[i] * cw[i];
    int hw = 2 * det - 1;
    for (int i = threadIdx.x; i < 2 * DMAX; i += CT) {
        float v = 0.0f;
        if (i < hw) { int d = i - (det - 1); if (d < 0) d = -d; v = g_h[d]; }
        h_ext[i] = v;
    }
    __syncthreads();

    const float qs = g_par[b].qscale;
    const int t  = threadIdx.x;
    const int k0 = t, k1 = t + CT, k2 = t + 2 * CT;
    const bool v1 = (k1 < det), v2 = (k2 < det);

    float acc0 = 0.5f * s_sh[k0];
    float acc1 = v1 ? 0.5f * s_sh[k1] : 0.0f;
    float acc2 = v2 ? 0.5f * s_sh[k2] : 0.0f;

    const int base = k0 + (det - 1);
    const int m0   = (t & 1) ^ 1;
#pragma unroll 4
    for (int m = m0; m < det; m += 2) {
        float sm = s_sh[m];
        int idx = base - m;
        acc0 = fmaf(sm, h_ext[idx],          acc0);
        acc1 = fmaf(sm, h_ext[idx + CT],     acc1);
        acc2 = fmaf(sm, h_ext[idx + 2 * CT], acc2);
    }

    // stage outputs in shared, then emit paired float2 table
    __syncthreads();
    s_sh[k0] = acc0 * qs;
    if (v1) s_sh[k1] = acc1 * qs;
    if (v2) s_sh[k2] = acc2 * qs;
    __syncthreads();

    float2* qr = g_q2 + ((size_t)b * A + a) * det;
    for (int i = threadIdx.x; i < det; i += CT) {
        int j = (i + 1 < det) ? i + 1 : det - 1;
        qr[i] = make_float2(s_sh[i], s_sh[j]);
    }
}

// ---------------------------------------------------------- backprojection -
__device__ __forceinline__ void bp_sample(const float2* __restrict__ qr,
                                          float U, float T,
                                          float center, float detm1, float dso2,
                                          float& acc) {
    float r  = __fdividef(1.0f, U);
    float u  = fmaf(T, r, center);
    float uc = fminf(fmaxf(u, 0.0f), detm1);
    float fi = floorf(uc);
    int   i  = (int)fi;
    float w  = uc - fi;
    float2 q = __ldg(qr + i);
    float lerp = fmaf(w, q.y - q.x, q.x);
    float g = dso2 * (r * r);
    g = (u == uc) ? g : 0.0f;
    acc = fmaf(lerp, g, acc);
}

// Block (32,8) handles a 32x16 pixel tile (2 pixels/thread along y, spacing 8).
__global__ __launch_bounds__(256) void bp_kernel(float* __restrict__ out,
                                                 int A, int det, int N) {
    int b = blockIdx.z;
    __shared__ float4 sc[AMAX];
    int tid = threadIdx.y * 32 + threadIdx.x;
    for (int a = tid; a < A; a += 256) sc[a] = g_sc4[b * A + a];
    __syncthreads();

    BParams p = g_par[b];
    int x  = blockIdx.x * 32 + threadIdx.x;
    int y0 = blockIdx.y * 16 + threadIdx.y;

    float half = 0.5f * (float)(N - 1);
    float X  = (float)x  - half;
    float Y0 = (float)y0 - half;
    float Xp = p.c1 * X;      // fold c1 into coords: u = t'/U + center
    float Yp = p.c1 * Y0;
    const float detm1  = (float)(det - 1);
    const float dso2   = p.dso2;
    const float dso_s  = p.dso_s;
    const float center = p.center;

    float acc0 = 0.0f, acc1 = 0.0f;
    const float2* __restrict__ qr = g_q2 + (size_t)b * A * det;

#pragma unroll 4
    for (int a = 0; a < A; a++) {
        float4 s = sc[a];
        float U0 = fmaf(-Y0, s.y, fmaf(X, s.x, dso_s));  // dso_s + X sin - Y cos
        float T0 = fmaf(Xp, s.y, Yp * s.x);              // c1*(X cos + Y sin)
        float U1 = U0 + s.z;                             // -8*cos
        float T1 = T0 + s.w;                             // +8*c1*sin
        bp_sample(qr, U0, T0, center, detm1, dso2, acc0);
        bp_sample(qr, U1, T1, center, detm1, dso2, acc1);
        qr += det;
    }

    size_t obase = (size_t)b * N * N;
    out[obase + (size_t)(y0    ) * N + x] = (acc0 - p.hu0) * p.oscale;
    out[obase + (size_t)(y0 + 8) * N + x] = (acc1 - p.hu0) * p.oscale;
}

// ----------------------------------------------------------------- launch --
extern "C" void kernel_launch(void* const* d_in, const int* in_sizes, int n_in,
                              void* d_out, int out_size) {
    const float* sino   = (const float*)d_in[0];   // (B,1,A,DET)
    const float* angles = (const float*)d_in[1];   // (B,A_hr)
    const float* dso    = (const float*)d_in[2];
    const float* ddo    = (const float*)d_in[3];
    const float* du     = (const float*)d_in[4];
    const float* hu     = (const float*)d_in[5];
    float* out = (float*)d_out;

    int B   = in_sizes[2];
    int Ahr = in_sizes[1] / B;
    int Asr = Ahr;
    int det = in_sizes[0] / (B * Asr);
    int per = out_size / B;
    int N = 1; while (N * N < per) N++;

    fill_h_kernel<<<1, 256>>>(det);
    prep_kernel<<<B, 256>>>(angles, dso, ddo, du, hu, Ahr, Asr, det);
    conv_kernel<<<dim3(Asr, B), CT>>>(sino, Asr, det);
    dim3 grid((N + 31) / 32, (N + 15) / 16, B);
    bp_kernel<<<grid, dim3(32, 8)>>>(out, Asr, det, N);
}

// round 4
// speedup vs baseline: 1.4417x; 1.1277x over previous
#include <cuda_runtime.h>
#include <math.h>

// ---------------------------------------------------------------------------
// DifferentiableFBP: ramp-filtered backprojection (fan-beam FBP)
// Stage 1 (prep):  per-batch scalars, per-angle packed (sin,sin,cos,cos),
//                  cos-weight table, spatial ram-lak taps (exact equivalent of
//                  the rfft pipeline: pure linear convolution, even taps zero).
// Stage 2 (conv):  filtered row conv (dso^2 folded into scale), paired
//                  float2 table q2[k]=(q[k],q[k+1]).
// Stage 3 (bp):    per pixel sum over angles, f32x2-packed math for the two
//                  y-samples per thread; lerp(q,u)*r^2 with predicated accum.
// ---------------------------------------------------------------------------

#define MAXB 4
#define AMAX 1536
#define DMAX 1024
#define CT   256   // conv block size (fixed, logic depends on it)

typedef unsigned long long ull;

__device__ __forceinline__ ull PK(float x, float y) {
    ull r; asm("mov.b64 %0, {%1, %2};" : "=l"(r) : "f"(x), "f"(y)); return r;
}
__device__ __forceinline__ void UPK(ull p, float& x, float& y) {
    asm("mov.b64 {%0, %1}, %2;" : "=f"(x), "=f"(y) : "l"(p));
}
__device__ __forceinline__ ull FMA2(ull a, ull b, ull c) {
    ull d; asm("fma.rn.f32x2 %0, %1, %2, %3;" : "=l"(d) : "l"(a), "l"(b), "l"(c)); return d;
}
__device__ __forceinline__ ull MUL2(ull a, ull b) {
    ull d; asm("mul.rn.f32x2 %0, %1, %2;" : "=l"(d) : "l"(a), "l"(b)); return d;
}

struct BParams {
    float dso_s;   // scaled source distance
    float c1;      // dso_s / du_v
    float center;  // (det-1)/2
    float qscale;  // vox * 0.5*dbeta / du_v * dso_s^2  (all scales folded)
    float hu0;
    float oscale;  // 1000/(hu0+1e-6)
};

__device__ BParams g_par[MAXB];
__device__ float   g_h[DMAX];
__device__ float4  g_sc4[MAXB * AMAX];       // (sin, sin, cos, cos)
__device__ float   g_cosw[MAXB * DMAX];
__device__ float2  g_q2[MAXB * AMAX * DMAX]; // paired filtered sinogram

// ---------------------------------------------------------------- taps -----
__global__ void fill_h_kernel(int det) {
    for (int d = threadIdx.x; d < det; d += blockDim.x) {
        double v;
        if (d == 0)      v = 0.5;
        else if (d & 1) { double pd = 3.14159265358979323846 * (double)d;
                          v = -2.0 / (pd * pd); }
        else             v = 0.0;
        g_h[d] = (float)v;
    }
}

// ------------------------------------------------------------- per-batch ---
__global__ void prep_kernel(const float* __restrict__ angles,
                            const float* __restrict__ dso,
                            const float* __restrict__ ddo,
                            const float* __restrict__ du,
                            const float* __restrict__ hu,
                            int Ahr, int Asr, int det) {
    int b = blockIdx.x;
    __shared__ float sh[4];
    if (threadIdx.x == 0) {
        const float vox = 1.0f / 0.7f;
        float dso_s = vox * dso[b];
        float sd_s  = vox * (dso[b] + ddo[b]);
        float du_s  = vox * du[b];
        float du_v  = du_s * dso_s / sd_s;
        float a0    = angles[(size_t)b * Ahr];
        float inc   = angles[(size_t)b * Ahr + 1] - a0;
        float dbeta = ((float)Ahr * inc) / (float)Asr;

        BParams p;
        p.dso_s  = dso_s;
        p.c1     = dso_s / du_v;
        p.center = 0.5f * (float)(det - 1);
        p.qscale = (vox * 0.5f * dbeta / du_v) * (dso_s * dso_s);
        float h0 = fmaxf(fabsf(hu[b]), 1e-6f);
        p.hu0    = h0;
        p.oscale = 1000.0f / (h0 + 1e-6f);
        g_par[b] = p;

        sh[0] = dso_s; sh[1] = du_v; sh[2] = a0; sh[3] = dbeta;
    }
    __syncthreads();
    float dso_s = sh[0], du_v = sh[1], a0 = sh[2], dbeta = sh[3];

    for (int a = threadIdx.x; a < Asr; a += blockDim.x) {
        float bta = a0 + dbeta * (float)a;
        float s = sinf(bta), c = cosf(bta);
        g_sc4[b * Asr + a] = make_float4(s, s, c, c);
    }
    for (int m = threadIdx.x; m < det; m += blockDim.x) {
        float uk = ((float)m - 0.5f * (float)(det - 1)) * du_v;
        g_cosw[b * det + m] = dso_s / sqrtf(dso_s * dso_s + uk * uk);
    }
}

// ------------------------------------------------------------- filtering ---
// One block per (angle,batch) row. 256 threads, 3 outputs per thread.
// h zero at even |d| != 0 -> only detector samples of opposite parity.
__global__ __launch_bounds__(CT) void conv_kernel(const float* __restrict__ sino,
                                                  int A, int det) {
    int a = blockIdx.x, b = blockIdx.y;
    __shared__ float s_sh[DMAX];
    __shared__ float h_ext[2 * DMAX];

    const float* row = sino + ((size_t)b * A + a) * det;
    const float* cw  = g_cosw + b * det;
    for (int i = threadIdx.x; i < det; i += CT)
        s_sh[i] = row[i] * cw[i];
    int hw = 2 * det - 1;
    for (int i = threadIdx.x; i < 2 * DMAX; i += CT) {
        float v = 0.0f;
        if (i < hw) { int d = i - (det - 1); if (d < 0) d = -d; v = g_h[d]; }
        h_ext[i] = v;
    }
    __syncthreads();

    const float qs = g_par[b].qscale;
    const int t  = threadIdx.x;
    const int k0 = t, k1 = t + CT, k2 = t + 2 * CT;
    const bool v1 = (k1 < det), v2 = (k2 < det);

    float acc0 = 0.5f * s_sh[k0];
    float acc1 = v1 ? 0.5f * s_sh[k1] : 0.0f;
    float acc2 = v2 ? 0.5f * s_sh[k2] : 0.0f;

    const int base = k0 + (det - 1);
    const int m0   = (t & 1) ^ 1;
#pragma unroll 4
    for (int m = m0; m < det; m += 2) {
        float sm = s_sh[m];
        int idx = base - m;
        acc0 = fmaf(sm, h_ext[idx],          acc0);
        acc1 = fmaf(sm, h_ext[idx + CT],     acc1);
        acc2 = fmaf(sm, h_ext[idx + 2 * CT], acc2);
    }

    // stage outputs in shared, then emit paired float2 table
    __syncthreads();
    s_sh[k0] = acc0 * qs;
    if (v1) s_sh[k1] = acc1 * qs;
    if (v2) s_sh[k2] = acc2 * qs;
    __syncthreads();

    float2* qr = g_q2 + ((size_t)b * A + a) * det;
    for (int i = threadIdx.x; i < det; i += CT) {
        int j = (i + 1 < det) ? i + 1 : det - 1;
        qr[i] = make_float2(s_sh[i], s_sh[j]);
    }
}

// ---------------------------------------------------------- backprojection -
// Block (32,4) handles a 32x8 pixel tile (2 pixels/thread along y, spacing 4).
// Both samples travel through packed f32x2 ops until the gather.
__global__ __launch_bounds__(128) void bp_kernel(float* __restrict__ out,
                                                 int A, int det, int N) {
    int b = blockIdx.z;
    __shared__ ulonglong2 sc[AMAX];   // .x = (sin,sin)  .y = (cos,cos)
    int tid = threadIdx.y * 32 + threadIdx.x;
    for (int a = tid; a < A; a += 128) {
        float4 v = g_sc4[b * A + a];
        ulonglong2 e;
        e.x = PK(v.x, v.y);
        e.y = PK(v.z, v.w);
        sc[a] = e;
    }
    __syncthreads();

    BParams p = g_par[b];
    int x  = blockIdx.x * 32 + threadIdx.x;
    int y0 = blockIdx.y * 8 + threadIdx.y;

    float half = 0.5f * (float)(N - 1);
    float X  = (float)x  - half;
    float Y0 = (float)y0 - half;
    float Y1 = Y0 + 4.0f;

    const ull X2  = PK(X, X);
    const ull nY2 = PK(-Y0, -Y1);
    const ull Xp2 = PK(p.c1 * X,  p.c1 * X);
    const ull Yp2 = PK(p.c1 * Y0, p.c1 * Y1);
    const ull D2  = PK(p.dso_s, p.dso_s);
    const ull C2  = PK(p.center, p.center);
    const float detm1 = (float)(det - 1);

    float acc0 = 0.0f, acc1 = 0.0f;
    const float2* __restrict__ qr = g_q2 + (size_t)b * A * det;

#pragma unroll 4
    for (int a = 0; a < A; a++) {
        ulonglong2 t = sc[a];
        ull U2 = FMA2(X2, t.x, FMA2(nY2, t.y, D2));   // dso + X sin - Y cos
        ull T2 = FMA2(Yp2, t.x, MUL2(Xp2, t.y));      // c1*(X cos + Y sin)
        float U0, U1; UPK(U2, U0, U1);
        float r0 = __fdividef(1.0f, U0);
        float r1 = __fdividef(1.0f, U1);
        ull R2 = PK(r0, r1);
        ull u2 = FMA2(T2, R2, C2);
        ull g2 = MUL2(R2, R2);
        float u0, u1; UPK(u2, u0, u1);
        float g0, g1; UPK(g2, g0, g1);

        {
            float uc = fminf(fmaxf(u0, 0.0f), detm1);
            float fi = floorf(uc);
            int   i  = (int)fi;
            float w  = uc - fi;
            float2 q = __ldg(qr + i);
            float lp = fmaf(w, q.y - q.x, q.x);
            if (u0 == uc) acc0 = fmaf(lp, g0, acc0);
        }
        {
            float uc = fminf(fmaxf(u1, 0.0f), detm1);
            float fi = floorf(uc);
            int   i  = (int)fi;
            float w  = uc - fi;
            float2 q = __ldg(qr + i);
            float lp = fmaf(w, q.y - q.x, q.x);
            if (u1 == uc) acc1 = fmaf(lp, g1, acc1);
        }
        qr += det;
    }

    size_t obase = (size_t)b * N * N;
    out[obase + (size_t)(y0    ) * N + x] = (acc0 - p.hu0) * p.oscale;
    out[obase + (size_t)(y0 + 4) * N + x] = (acc1 - p.hu0) * p.oscale;
}

// ----------------------------------------------------------------- launch --
extern "C" void kernel_launch(void* const* d_in, const int* in_sizes, int n_in,
                              void* d_out, int out_size) {
    const float* sino   = (const float*)d_in[0];   // (B,1,A,DET)
    const float* angles = (const float*)d_in[1];   // (B,A_hr)
    const float* dso    = (const float*)d_in[2];
    const float* ddo    = (const float*)d_in[3];
    const float* du     = (const float*)d_in[4];
    const float* hu     = (const float*)d_in[5];
    float* out = (float*)d_out;

    int B   = in_sizes[2];
    int Ahr = in_sizes[1] / B;
    int Asr = Ahr;
    int det = in_sizes[0] / (B * Asr);
    int per = out_size / B;
    int N = 1; while (N * N < per) N++;

    fill_h_kernel<<<1, 256>>>(det);
    prep_kernel<<<B, 256>>>(angles, dso, ddo, du, hu, Ahr, Asr, det);
    conv_kernel<<<dim3(Asr, B), CT>>>(sino, Asr, det);
    dim3 grid((N + 31) / 32, (N + 7) / 8, B);
    bp_kernel<<<grid, dim3(32, 4)>>>(out, Asr, det, N);
}